// round 12
// baseline (speedup 1.0000x reference)
#include <cuda_runtime.h>
#include <cuda_bf16.h>
#include <cstdint>
#include <cstddef>

// ---------------- problem constants ----------------
#define NTOK   98304      // 32768 * 3 tokens
#define DIM_D  256
#define DIM_E  512
#define DIM_H  512
#define DIM_C  64
#define NCODES 1024
#define DECAY_F 0.99f

// single extern shared decl (consistent type across all kernels)
extern __shared__ __align__(16) char g_smem_raw[];

// ---------------- scratch (device globals; no allocs allowed) ----------------
__device__ float g_bufA[NTOK * DIM_E];
__device__ float g_bufB[NTOK * DIM_H];
__device__ float g_dw[DIM_C * NCODES];
__device__ unsigned int g_counts[NCODES];
__device__ float g_norms[NCODES];
__device__ float g_loss[1];

// weights (L0..L2) pre-split into 3 bf16 planes, transposed [N,K] K-major
// offsets: L0 (N=512,K=256)=0, L1 (512,512)=131072, L2=393216 (end 655360)
#define WSPLIT_TOTAL 655360
__device__ __nv_bfloat16 g_wb1[WSPLIT_TOTAL];
__device__ __nv_bfloat16 g_wb2[WSPLIT_TOTAL];
__device__ __nv_bfloat16 g_wb3[WSPLIT_TOTAL];

// ---------------- small helpers ----------------
__device__ __forceinline__ uint32_t smem_u32(const void* p) {
    uint32_t a;
    asm("{ .reg .u64 t; cvta.to.shared.u64 t, %1; cvt.u32.u64 %0, t; }"
        : "=r"(a) : "l"(p));
    return a;
}
__device__ __forceinline__ float gelu_tanh(float x) {
    float x3 = x * x * x;
    float t = tanhf(0.7978845608028654f * (x + 0.044715f * x3));
    return 0.5f * x * (1.0f + t);
}
__device__ __forceinline__ void cp_async16(uint32_t saddr, const void* gptr) {
    asm volatile("cp.async.ca.shared.global [%0], [%1], 16;"
                 :: "r"(saddr), "l"(gptr) : "memory");
}
#define CP_COMMIT() asm volatile("cp.async.commit_group;" ::: "memory")
#define CP_WAIT0()  asm volatile("cp.async.wait_group 0;" ::: "memory")
#define CP_WAIT1()  asm volatile("cp.async.wait_group 1;" ::: "memory")

// exact 3-way bf16 split of fp32 (24 = 8+8+8 mantissa bits)
__device__ __forceinline__ void split3(float x, uint16_t& s1, uint16_t& s2, uint16_t& s3) {
    __nv_bfloat16 b1 = __float2bfloat16_rn(x);
    float r = x - __bfloat162float(b1);
    __nv_bfloat16 b2 = __float2bfloat16_rn(r);
    float r2 = r - __bfloat162float(b2);
    __nv_bfloat16 b3 = __float2bfloat16_rn(r2);
    s1 = *reinterpret_cast<uint16_t*>(&b1);
    s2 = *reinterpret_cast<uint16_t*>(&b2);
    s3 = *reinterpret_cast<uint16_t*>(&b3);
}

__device__ __forceinline__ void ldsm4(uint32_t& r0, uint32_t& r1, uint32_t& r2,
                                      uint32_t& r3, uint32_t addr) {
    asm volatile("ldmatrix.sync.aligned.m8n8.x4.shared.b16 {%0,%1,%2,%3}, [%4];"
                 : "=r"(r0), "=r"(r1), "=r"(r2), "=r"(r3) : "r"(addr));
}
__device__ __forceinline__ void mma16(float* c, const uint32_t* a, const uint32_t* b) {
    asm volatile(
        "mma.sync.aligned.m16n8k16.row.col.f32.bf16.bf16.f32 "
        "{%0,%1,%2,%3}, {%4,%5,%6,%7}, {%8,%9}, {%0,%1,%2,%3};"
        : "+f"(c[0]), "+f"(c[1]), "+f"(c[2]), "+f"(c[3])
        : "r"(a[0]), "r"(a[1]), "r"(a[2]), "r"(a[3]), "r"(b[0]), "r"(b[1]));
}

// f32x2 packed helpers (vq kernel)
__device__ __forceinline__ unsigned long long pack2(float lo, float hi) {
    unsigned long long r;
    asm("mov.b64 %0, {%1, %2};" : "=l"(r) : "f"(lo), "f"(hi));
    return r;
}
__device__ __forceinline__ unsigned long long fma2(unsigned long long a,
                                                   unsigned long long b,
                                                   unsigned long long c) {
    unsigned long long d;
    asm("fma.rn.f32x2 %0, %1, %2, %3;" : "=l"(d) : "l"(a), "l"(b), "l"(c));
    return d;
}
__device__ __forceinline__ float2 unpack2(unsigned long long v) {
    float lo, hi;
    asm("mov.b64 {%0, %1}, %2;" : "=f"(lo), "=f"(hi) : "l"(v));
    return make_float2(lo, hi);
}

// ---------------- bf16x3 six-pass GEMM, 3-stage pipeline, RN-safe folding ------
// O[M,N] = gelu(A[M,K] @ W[K,N] + bias). BM=BN=128, BK=16, 8 warps, warp 32x64.
// Arithmetic identical to R8 (proven rel_err 6.16e-7). Pipeline: 3 smem stages;
// top of iter t: STS_A(t+1)->(t+1)%3 (stage retired 2 barriers ago),
// CP_B(t+2)->(t+2)%3 (retired 1 barrier ago), LDG_A(t+2)->regs; compute t;
// wait_group keeps 1 B-load in flight; barrier.
__global__ void __launch_bounds__(256, 2)
mma_gemm_gelu(const float* __restrict__ A, const __nv_bfloat16* __restrict__ W1,
              const __nv_bfloat16* __restrict__ W2, const __nv_bfloat16* __restrict__ W3,
              const float* __restrict__ bias, float* __restrict__ O, int Kd, int Nn) {
    constexpr int MBLK = 2, NBLK = 8;
    constexpr int APLANE = 128 * 48;     // 6144 B
    constexpr int BPLANE = 128 * 48;
    constexpr int STAGE = 3 * APLANE + 3 * BPLANE;   // 36864 B; 3 stages total

    char* smem = g_smem_raw;
    const int tid = threadIdx.x;
    const int lane = tid & 31;
    const int wid = tid >> 5;
    const int wrow = wid >> 1;           // 0..3 -> 32-row strip
    const int wcol = wid & 1;            // 0..1 -> 64-col strip
    const int rowBase = blockIdx.y * 128;
    const int colBase = blockIdx.x * 128;
    const uint32_t sbase = smem_u32(smem);
    const int T = Kd / 16;

    float acc[MBLK][NBLK][4];
#pragma unroll
    for (int mb = 0; mb < MBLK; mb++)
#pragma unroll
        for (int nb = 0; nb < NBLK; nb++)
#pragma unroll
            for (int j = 0; j < 4; j++) acc[mb][nb][j] = 0.0f;

    float4 areg[2];

#define LDG_A(t)                                                                 \
    {                                                                            \
        _Pragma("unroll") for (int i = 0; i < 2; i++) {                          \
            int idx = tid + i * 256;                                             \
            int r = idx >> 2, kq = idx & 3;                                      \
            areg[i] = *reinterpret_cast<const float4*>(                          \
                &A[(size_t)(rowBase + r) * Kd + (t) * 16 + kq * 4]);             \
        }                                                                        \
    }

#define STS_A(s)                                                                 \
    {                                                                            \
        char* dst = smem + (s) * STAGE;                                          \
        _Pragma("unroll") for (int i = 0; i < 2; i++) {                          \
            int idx = tid + i * 256;                                             \
            int r = idx >> 2, kq = idx & 3;                                      \
            float4 v = areg[i];                                                  \
            uint16_t p1[4], p2[4], p3[4];                                        \
            split3(v.x, p1[0], p2[0], p3[0]);                                    \
            split3(v.y, p1[1], p2[1], p3[1]);                                    \
            split3(v.z, p1[2], p2[2], p3[2]);                                    \
            split3(v.w, p1[3], p2[3], p3[3]);                                    \
            int off = r * 48 + kq * 8;                                           \
            uint2 u;                                                             \
            u.x = (uint32_t)p1[0] | ((uint32_t)p1[1] << 16);                     \
            u.y = (uint32_t)p1[2] | ((uint32_t)p1[3] << 16);                     \
            *reinterpret_cast<uint2*>(dst + off) = u;                            \
            u.x = (uint32_t)p2[0] | ((uint32_t)p2[1] << 16);                     \
            u.y = (uint32_t)p2[2] | ((uint32_t)p2[3] << 16);                     \
            *reinterpret_cast<uint2*>(dst + APLANE + off) = u;                   \
            u.x = (uint32_t)p3[0] | ((uint32_t)p3[1] << 16);                     \
            u.y = (uint32_t)p3[2] | ((uint32_t)p3[3] << 16);                     \
            *reinterpret_cast<uint2*>(dst + 2 * APLANE + off) = u;               \
        }                                                                        \
    }

#define CP_B(t, s)                                                               \
    {                                                                            \
        uint32_t bb = sbase + (s) * STAGE + 3 * APLANE;                          \
        _Pragma("unroll") for (int i = 0; i < 3; i++) { /* 768 chunks */         \
            int idx = tid + i * 256;                                             \
            int plane = idx >> 8;                                                \
            int rest = idx & 255;                                                \
            int n = rest >> 1, half = rest & 1;                                  \
            const __nv_bfloat16* src =                                           \
                (plane == 0 ? W1 : plane == 1 ? W2 : W3) +                       \
                (size_t)(colBase + n) * Kd + (t) * 16 + half * 8;                \
            cp_async16(bb + plane * BPLANE + n * 48 + half * 16, src);           \
        }                                                                        \
    }

    // prologue: stage0 A+B, stage1 B; A(1) staged in regs
    LDG_A(0);
    STS_A(0);
    CP_B(0, 0);
    CP_COMMIT();
    if (T > 1) {
        CP_B(1, 1);
        CP_COMMIT();
        LDG_A(1);
        CP_WAIT1();          // B(0) done, B(1) in flight
    } else {
        CP_WAIT0();
    }
    __syncthreads();

    const uint32_t aOffL = (uint32_t)((wrow * 32 + (lane & 15)) * 48 + (lane >> 4) * 16);
    const uint32_t bOff4 = (uint32_t)((wcol * 64 + ((lane >> 4) & 1) * 8 + (lane & 7)) * 48 +
                                      ((lane >> 3) & 1) * 16);

    for (int t = 0; t < T; t++) {
        const int s = t % 3;
        if (t + 1 < T) STS_A((t + 1) % 3);                 // stage retired 2 barriers ago
        if (t + 2 < T) {
            CP_B(t + 2, (t + 2) % 3);                      // stage retired 1 barrier ago
            CP_COMMIT();
            LDG_A(t + 2);
        }

        // compute stage s (identical arithmetic to R8)
        {
            const uint32_t abase = sbase + s * STAGE;
            const uint32_t bbase = abase + 3 * APLANE;
            uint32_t a[3][MBLK][4];
#pragma unroll
            for (int pa = 0; pa < 3; pa++)
#pragma unroll
                for (int mb = 0; mb < MBLK; mb++)
                    ldsm4(a[pa][mb][0], a[pa][mb][1], a[pa][mb][2], a[pa][mb][3],
                          abase + pa * APLANE + aOffL + mb * 16 * 48);

#pragma unroll
            for (int nb2 = 0; nb2 < 4; nb2++) {
                uint32_t b[3][2][2];
#pragma unroll
                for (int pb = 0; pb < 3; pb++) {
                    uint32_t r0, r1, r2, r3;
                    ldsm4(r0, r1, r2, r3, bbase + pb * BPLANE + bOff4 + nb2 * 16 * 48);
                    b[pb][0][0] = r0; b[pb][0][1] = r1;
                    b[pb][1][0] = r2; b[pb][1][1] = r3;
                }
#pragma unroll
                for (int sub = 0; sub < 2; sub++) {
                    const int nb = nb2 * 2 + sub;
#pragma unroll
                    for (int mb = 0; mb < MBLK; mb++) {
                        float dl[4] = {0.f, 0.f, 0.f, 0.f};
                        mma16(dl, a[1][mb], b[1][sub]);   // mid*mid
                        mma16(dl, a[2][mb], b[0][sub]);   // lo*hi
                        mma16(dl, a[0][mb], b[2][sub]);   // hi*lo
                        mma16(dl, a[1][mb], b[0][sub]);   // mid*hi
                        mma16(dl, a[0][mb], b[1][sub]);   // hi*mid
                        float dh[4] = {0.f, 0.f, 0.f, 0.f};
                        mma16(dh, a[0][mb], b[0][sub]);   // hi*hi
#pragma unroll
                        for (int j = 0; j < 4; j++)
                            acc[mb][nb][j] += (dh[j] + dl[j]);   // FADD.RN
                    }
                }
            }
        }
        if (t + 1 < T) {
            if (t + 2 < T) CP_WAIT1();   // B(t+1) done, B(t+2) in flight
            else CP_WAIT0();             // last prefetch: drain fully
        }
        __syncthreads();
    }
#undef LDG_A
#undef STS_A
#undef CP_B

    // epilogue: bias + gelu, float2 stores (identical to R8)
#pragma unroll
    for (int mb = 0; mb < MBLK; mb++) {
        int r0 = rowBase + wrow * 32 + mb * 16 + (lane >> 2);
#pragma unroll
        for (int nb = 0; nb < NBLK; nb++) {
            int c = colBase + wcol * 64 + nb * 8 + (lane & 3) * 2;
            float b0 = __ldg(&bias[c]);
            float b1 = __ldg(&bias[c + 1]);
            float2 v0, v1;
            v0.x = gelu_tanh(acc[mb][nb][0] + b0);
            v0.y = gelu_tanh(acc[mb][nb][1] + b1);
            v1.x = gelu_tanh(acc[mb][nb][2] + b0);
            v1.y = gelu_tanh(acc[mb][nb][3] + b1);
            *reinterpret_cast<float2*>(&O[(size_t)r0 * Nn + c]) = v0;
            *reinterpret_cast<float2*>(&O[(size_t)(r0 + 8) * Nn + c]) = v1;
        }
    }
}

// ---------------- weight transpose + exact bf16x3 split ----------------
__global__ void split_w_kernel(const float* __restrict__ W, __nv_bfloat16* __restrict__ o1,
                               __nv_bfloat16* __restrict__ o2, __nv_bfloat16* __restrict__ o3,
                               int K, int N) {
    int i = blockIdx.x * 256 + threadIdx.x;
    if (i >= K * N) return;
    int k = i / N, n = i - k * N;
    float v = W[i];
    uint16_t s1, s2, s3;
    split3(v, s1, s2, s3);
    size_t o = (size_t)n * K + k;
    o1[o] = *reinterpret_cast<__nv_bfloat16*>(&s1);
    o2[o] = *reinterpret_cast<__nv_bfloat16*>(&s2);
    o3[o] = *reinterpret_cast<__nv_bfloat16*>(&s3);
}

// ---------------- prep: zero accumulators, code norms ----------------
__global__ void prep_kernel(const float* __restrict__ emb) {
    int gid = blockIdx.x * 1024 + threadIdx.x;
    if (gid < DIM_C * NCODES) g_dw[gid] = 0.0f;
    if (blockIdx.x == 0) {
        int k = threadIdx.x;
        g_counts[k] = 0u;
        float s = 0.0f;
#pragma unroll
        for (int c = 0; c < DIM_C; c++) {
            float v = emb[(size_t)c * NCODES + k];
            s += v * v;
        }
        g_norms[k] = s;
        if (k == 0) g_loss[0] = 0.0f;
    }
}

// ---------------- fused L3 GEMM + VQ (bit-exact fp32 path) ----------------
#define VQ_AS_F     (128 * 64)
#define VQ_AT_F     (32 * 132)
#define VQ_WT_F     (32 * 68)
#define VQ_SMEM_B   (VQ_AS_F * 4 + (VQ_AT_F + VQ_WT_F) * 4)

__global__ void __launch_bounds__(256, 2)
vq_fused_kernel(const float* __restrict__ X, const float* __restrict__ w2,
                const float* __restrict__ b2v, const float* __restrict__ emb,
                float* __restrict__ outQ, float* __restrict__ outIdx) {
    constexpr int BM = 128, CD = 64, BN = 64, NT = NCODES / BN;
    float* smem = reinterpret_cast<float*>(g_smem_raw);
    float* As = smem;
    float* At = smem + VQ_AS_F;
    float* Wt = At + VQ_AT_F;
    float* shb = smem + VQ_AS_F;
    int*   shIdx = reinterpret_cast<int*>(smem + VQ_AS_F);
    float* shRed = smem + VQ_AS_F + 128;

    const int tid = threadIdx.x;
    const int tx = tid & 15;
    const int ty = tid >> 4;
    const int base = blockIdx.x * BM;

    // phase 1: latent = gelu(X @ w2 + b2)
    {
        unsigned long long acc[8][2];
#pragma unroll
        for (int m = 0; m < 8; m++) { acc[m][0] = 0ull; acc[m][1] = 0ull; }

        for (int kc = 0; kc < DIM_H / 32; kc++) {
#pragma unroll
            for (int i = 0; i < 4; i++) {
                int idx = tid + i * 256;
                int r = idx >> 3, kq = idx & 7;
                float4 v = *reinterpret_cast<const float4*>(
                    &X[(size_t)(base + r) * DIM_H + kc * 32 + kq * 4]);
                At[(kq * 4 + 0) * 132 + r] = v.x;
                At[(kq * 4 + 1) * 132 + r] = v.y;
                At[(kq * 4 + 2) * 132 + r] = v.z;
                At[(kq * 4 + 3) * 132 + r] = v.w;
            }
#pragma unroll
            for (int i = 0; i < 2; i++) {
                int idx = tid + i * 256;
                int krow = idx >> 4, nq = idx & 15;
                *reinterpret_cast<float4*>(&Wt[krow * 68 + nq * 4]) =
                    *reinterpret_cast<const float4*>(
                        &w2[(size_t)(kc * 32 + krow) * DIM_C + nq * 4]);
            }
            __syncthreads();
#pragma unroll 8
            for (int kk = 0; kk < 32; kk++) {
                float4 a0 = *reinterpret_cast<const float4*>(&At[kk * 132 + ty * 8]);
                float4 a1 = *reinterpret_cast<const float4*>(&At[kk * 132 + ty * 8 + 4]);
                float av[8] = {a0.x, a0.y, a0.z, a0.w, a1.x, a1.y, a1.z, a1.w};
                float4 bv = *reinterpret_cast<const float4*>(&Wt[kk * 68 + tx * 4]);
                unsigned long long b20 = pack2(bv.x, bv.y);
                unsigned long long b21 = pack2(bv.z, bv.w);
#pragma unroll
                for (int m = 0; m < 8; m++) {
                    unsigned long long a2 = pack2(av[m], av[m]);
                    acc[m][0] = fma2(a2, b20, acc[m][0]);
                    acc[m][1] = fma2(a2, b21, acc[m][1]);
                }
            }
            __syncthreads();
        }
#pragma unroll
        for (int m = 0; m < 8; m++) {
            int row = ty * 8 + m;
#pragma unroll
            for (int n = 0; n < 2; n++) {
                int col = tx * 4 + n * 2;
                float2 v = unpack2(acc[m][n]);
                float2 o;
                o.x = gelu_tanh(v.x + b2v[col]);
                o.y = gelu_tanh(v.y + b2v[col + 1]);
                *reinterpret_cast<float2*>(&As[row * CD + col]) = o;
            }
        }
    }
    __syncthreads();

    // phase 2: VQ
    float best[8];
    int bidx[8];
#pragma unroll
    for (int m = 0; m < 8; m++) { best[m] = -3.4e38f; bidx[m] = 0; }

    for (int t = 0; t < NT; t++) {
        __syncthreads();
#pragma unroll
        for (int it = 0; it < 4; it++) {
            int idx = tid + it * 256;
            int c = idx >> 4;
            int jq = idx & 15;
            *reinterpret_cast<float4*>(&shb[c * BN + jq * 4]) =
                *reinterpret_cast<const float4*>(&emb[(size_t)c * NCODES + t * BN + jq * 4]);
        }
        __syncthreads();

        unsigned long long acc[8][2];
#pragma unroll
        for (int m = 0; m < 8; m++) { acc[m][0] = 0ull; acc[m][1] = 0ull; }

#pragma unroll 4
        for (int c = 0; c < CD; c++) {
            float4 bv = *reinterpret_cast<const float4*>(&shb[c * BN + tx * 4]);
            unsigned long long b20 = pack2(bv.x, bv.y);
            unsigned long long b21 = pack2(bv.z, bv.w);
#pragma unroll
            for (int m = 0; m < 8; m++) {
                float a = As[(ty * 8 + m) * CD + c];
                unsigned long long a2 = pack2(a, a);
                acc[m][0] = fma2(a2, b20, acc[m][0]);
                acc[m][1] = fma2(a2, b21, acc[m][1]);
            }
        }

        int cbase = t * BN + tx * 4;
        float n0 = __ldg(&g_norms[cbase + 0]);
        float n1 = __ldg(&g_norms[cbase + 1]);
        float n2 = __ldg(&g_norms[cbase + 2]);
        float n3 = __ldg(&g_norms[cbase + 3]);
#pragma unroll
        for (int m = 0; m < 8; m++) {
            float2 s0 = unpack2(acc[m][0]);
            float2 s1 = unpack2(acc[m][1]);
            float sc;
            sc = 2.0f * s0.x - n0; if (sc > best[m]) { best[m] = sc; bidx[m] = cbase + 0; }
            sc = 2.0f * s0.y - n1; if (sc > best[m]) { best[m] = sc; bidx[m] = cbase + 1; }
            sc = 2.0f * s1.x - n2; if (sc > best[m]) { best[m] = sc; bidx[m] = cbase + 2; }
            sc = 2.0f * s1.y - n3; if (sc > best[m]) { best[m] = sc; bidx[m] = cbase + 3; }
        }
    }

#pragma unroll
    for (int m = 0; m < 8; m++) {
#pragma unroll
        for (int off = 8; off > 0; off >>= 1) {
            float ob = __shfl_xor_sync(0xffffffffu, best[m], off);
            int oi = __shfl_xor_sync(0xffffffffu, bidx[m], off);
            if (ob > best[m] || (ob == best[m] && oi < bidx[m])) { best[m] = ob; bidx[m] = oi; }
        }
    }
    __syncthreads();
    if (tx == 0) {
#pragma unroll
        for (int m = 0; m < 8; m++) shIdx[ty * 8 + m] = bidx[m];
    }
    __syncthreads();

    if (tid < BM) {
        int id = shIdx[tid];
        outIdx[base + tid] = (float)id;
        atomicAdd(&g_counts[id], 1u);
    }
    float lsum = 0.0f;
#pragma unroll 8
    for (int it = 0; it < 32; it++) {
        int i = tid + it * 256;
        int row = i >> 6;
        int c = i & 63;
        int id = shIdx[row];
        float l = As[row * CD + c];
        float q = __ldg(&emb[(size_t)c * NCODES + id]);
        outQ[(size_t)(base + row) * CD + c] = l + (q - l);
        float d = q - l;
        lsum += d * d;
        atomicAdd(&g_dw[(size_t)c * NCODES + id], l);
    }
    shRed[tid] = lsum;
    __syncthreads();
    for (int s = 128; s > 0; s >>= 1) {
        if (tid < s) shRed[tid] += shRed[tid + s];
        __syncthreads();
    }
    if (tid == 0) atomicAdd(&g_loss[0], shRed[0]);
}

// ---------------- finalize ----------------
__global__ void __launch_bounds__(1024)
finalize_kernel(const float* __restrict__ ema_cluster,
                const float* __restrict__ ema_dw,
                float* __restrict__ out) {
    constexpr size_t LOSS_OFF = (size_t)NTOK * DIM_C;
    constexpr size_t PERP_OFF = LOSS_OFF + 1;
    constexpr size_t IDX_OFF = PERP_OFF + 1;
    constexpr size_t EMB_OFF = IDX_OFF + (size_t)NTOK;

    __shared__ float red[1024];
    int k = threadIdx.x;
    float debias = (float)(1.0 - pow(0.99, 1001.0));

    float cnt = (float)g_counts[k];
    float clh = ema_cluster[k] * DECAY_F + cnt * (1.0f - DECAY_F);
    float cs = clh / debias;

    red[k] = cs;
    __syncthreads();
    for (int s = 512; s > 0; s >>= 1) {
        if (k < s) red[k] += red[k + s];
        __syncthreads();
    }
    float n = red[0];
    __syncthreads();

    float p = cnt / (float)NTOK;
    red[k] = p * logf(p + 1e-10f);
    __syncthreads();
    for (int s = 512; s > 0; s >>= 1) {
        if (k < s) red[k] += red[k + s];
        __syncthreads();
    }
    float pl = red[0];

    float stable = (cs + 1e-5f) / (n + (float)NCODES * 1e-5f) * n;
#pragma unroll 4
    for (int c = 0; c < DIM_C; c++) {
        size_t i = (size_t)c * NCODES + k;
        float upd = (ema_dw[i] * DECAY_F + g_dw[i] * (1.0f - DECAY_F)) / debias;
        out[EMB_OFF + i] = upd / stable;
    }
    if (k == 0) {
        out[LOSS_OFF] = 0.25f * (g_loss[0] / ((float)NTOK * (float)DIM_C));
        out[PERP_OFF] = expf(-pl);
    }
}

// ---------------- launch ----------------
extern "C" void kernel_launch(void* const* d_in, const int* in_sizes, int n_in,
                              void* d_out, int out_size) {
    const float* states = (const float*)d_in[0];
    const float* w_se = (const float*)d_in[1];
    const float* b_se = (const float*)d_in[2];
    const float* w0 = (const float*)d_in[3];
    const float* b0 = (const float*)d_in[4];
    const float* w1 = (const float*)d_in[5];
    const float* b1 = (const float*)d_in[6];
    const float* w2 = (const float*)d_in[7];
    const float* b2 = (const float*)d_in[8];
    const float* emb = (const float*)d_in[9];
    const float* ema_cluster = (const float*)d_in[10];
    const float* ema_dw = (const float*)d_in[11];
    float* out = (float*)d_out;

    float *bufA, *bufB;
    __nv_bfloat16 *wb1, *wb2, *wb3;
    cudaGetSymbolAddress((void**)&bufA, g_bufA);
    cudaGetSymbolAddress((void**)&bufB, g_bufB);
    cudaGetSymbolAddress((void**)&wb1, g_wb1);
    cudaGetSymbolAddress((void**)&wb2, g_wb2);
    cudaGetSymbolAddress((void**)&wb3, g_wb3);

    const size_t IDX_OFF = (size_t)NTOK * DIM_C + 2;

    const int MMA_SMEM = 3 * (3 * 128 * 48 + 3 * 128 * 48);  // 110592 (3 stages)
    cudaFuncSetAttribute(mma_gemm_gelu,
                         cudaFuncAttributeMaxDynamicSharedMemorySize, MMA_SMEM);
    cudaFuncSetAttribute(vq_fused_kernel,
                         cudaFuncAttributeMaxDynamicSharedMemorySize, VQ_SMEM_B);

    // weight transpose + bf16x3 split for L0..L2
    split_w_kernel<<<(DIM_D * DIM_E + 255) / 256, 256>>>(w_se, wb1, wb2, wb3, DIM_D, DIM_E);
    split_w_kernel<<<(DIM_E * DIM_H + 255) / 256, 256>>>(w0, wb1 + 131072, wb2 + 131072,
                                                         wb3 + 131072, DIM_E, DIM_H);
    split_w_kernel<<<(DIM_H * DIM_H + 255) / 256, 256>>>(w1, wb1 + 393216, wb2 + 393216,
                                                         wb3 + 393216, DIM_H, DIM_H);
    prep_kernel<<<64, 1024>>>(emb);

    dim3 blk(256);
    mma_gemm_gelu<<<dim3(DIM_E / 128, NTOK / 128), blk, MMA_SMEM>>>(
        states, wb1, wb2, wb3, b_se, bufA, DIM_D, DIM_E);
    mma_gemm_gelu<<<dim3(DIM_H / 128, NTOK / 128), blk, MMA_SMEM>>>(
        bufA, wb1 + 131072, wb2 + 131072, wb3 + 131072, b0, bufB, DIM_E, DIM_H);
    mma_gemm_gelu<<<dim3(DIM_H / 128, NTOK / 128), blk, MMA_SMEM>>>(
        bufB, wb1 + 393216, wb2 + 393216, wb3 + 393216, b1, bufA, DIM_H, DIM_H);

    vq_fused_kernel<<<NTOK / 128, blk, VQ_SMEM_B>>>(
        bufA, w2, b2, emb, out /*quantized*/, out + IDX_OFF);
    finalize_kernel<<<1, 1024>>>(ema_cluster, ema_dw, out);
}

// round 13
// speedup vs baseline: 1.2175x; 1.2175x over previous
#include <cuda_runtime.h>
#include <cuda_bf16.h>
#include <cstdint>
#include <cstddef>

// ---------------- problem constants ----------------
#define NTOK   98304      // 32768 * 3 tokens
#define DIM_D  256
#define DIM_E  512
#define DIM_H  512
#define DIM_C  64
#define NCODES 1024
#define DECAY_F 0.99f

// single extern shared decl (consistent type across all kernels)
extern __shared__ __align__(16) char g_smem_raw[];

// ---------------- scratch (device globals; no allocs allowed) ----------------
__device__ float g_bufA[NTOK * DIM_E];
__device__ float g_bufB[NTOK * DIM_H];
__device__ float g_dw[DIM_C * NCODES];
__device__ unsigned int g_counts[NCODES];
__device__ float g_norms[NCODES];
__device__ float g_loss[1];

// weights (L0..L2) pre-split into 3 bf16 planes, transposed [N,K] K-major
// offsets: L0 (N=512,K=256)=0, L1 (512,512)=131072, L2=393216 (end 655360)
#define WSPLIT_TOTAL 655360
__device__ __nv_bfloat16 g_wb1[WSPLIT_TOTAL];
__device__ __nv_bfloat16 g_wb2[WSPLIT_TOTAL];
__device__ __nv_bfloat16 g_wb3[WSPLIT_TOTAL];

// ---------------- small helpers ----------------
__device__ __forceinline__ uint32_t smem_u32(const void* p) {
    uint32_t a;
    asm("{ .reg .u64 t; cvta.to.shared.u64 t, %1; cvt.u32.u64 %0, t; }"
        : "=r"(a) : "l"(p));
    return a;
}
__device__ __forceinline__ float gelu_tanh(float x) {
    float x3 = x * x * x;
    float t = tanhf(0.7978845608028654f * (x + 0.044715f * x3));
    return 0.5f * x * (1.0f + t);
}
__device__ __forceinline__ void cp_async16(uint32_t saddr, const void* gptr) {
    asm volatile("cp.async.ca.shared.global [%0], [%1], 16;"
                 :: "r"(saddr), "l"(gptr) : "memory");
}
#define CP_COMMIT() asm volatile("cp.async.commit_group;" ::: "memory")
#define CP_WAIT0()  asm volatile("cp.async.wait_group 0;" ::: "memory")

// exact 3-way bf16 split of fp32 (24 = 8+8+8 mantissa bits)
__device__ __forceinline__ void split3(float x, uint16_t& s1, uint16_t& s2, uint16_t& s3) {
    __nv_bfloat16 b1 = __float2bfloat16_rn(x);
    float r = x - __bfloat162float(b1);
    __nv_bfloat16 b2 = __float2bfloat16_rn(r);
    float r2 = r - __bfloat162float(b2);
    __nv_bfloat16 b3 = __float2bfloat16_rn(r2);
    s1 = *reinterpret_cast<uint16_t*>(&b1);
    s2 = *reinterpret_cast<uint16_t*>(&b2);
    s3 = *reinterpret_cast<uint16_t*>(&b3);
}

__device__ __forceinline__ void ldsm4(uint32_t& r0, uint32_t& r1, uint32_t& r2,
                                      uint32_t& r3, uint32_t addr) {
    asm volatile("ldmatrix.sync.aligned.m8n8.x4.shared.b16 {%0,%1,%2,%3}, [%4];"
                 : "=r"(r0), "=r"(r1), "=r"(r2), "=r"(r3) : "r"(addr));
}
__device__ __forceinline__ void ldsm2(uint32_t& r0, uint32_t& r1, uint32_t addr) {
    asm volatile("ldmatrix.sync.aligned.m8n8.x2.shared.b16 {%0,%1}, [%2];"
                 : "=r"(r0), "=r"(r1) : "r"(addr));
}
__device__ __forceinline__ void mma16(float* c, const uint32_t* a, const uint32_t* b) {
    asm volatile(
        "mma.sync.aligned.m16n8k16.row.col.f32.bf16.bf16.f32 "
        "{%0,%1,%2,%3}, {%4,%5,%6,%7}, {%8,%9}, {%0,%1,%2,%3};"
        : "+f"(c[0]), "+f"(c[1]), "+f"(c[2]), "+f"(c[3])
        : "r"(a[0]), "r"(a[1]), "r"(a[2]), "r"(a[3]), "r"(b[0]), "r"(b[1]));
}

// f32x2 packed helpers (vq kernel)
__device__ __forceinline__ unsigned long long pack2(float lo, float hi) {
    unsigned long long r;
    asm("mov.b64 %0, {%1, %2};" : "=l"(r) : "f"(lo), "f"(hi));
    return r;
}
__device__ __forceinline__ unsigned long long fma2(unsigned long long a,
                                                   unsigned long long b,
                                                   unsigned long long c) {
    unsigned long long d;
    asm("fma.rn.f32x2 %0, %1, %2, %3;" : "=l"(d) : "l"(a), "l"(b), "l"(c));
    return d;
}
__device__ __forceinline__ float2 unpack2(unsigned long long v) {
    float lo, hi;
    asm("mov.b64 {%0, %1}, %2;" : "=f"(lo), "=f"(hi) : "l"(v));
    return make_float2(lo, hi);
}

// ---------------- bf16x3 six-pass GEMM, merged-chain fold (R8 skeleton) --------
// O[M,N] = gelu(A[M,K] @ W[K,N] + bias). BM=BN=128, BK=16, 8 warps, warp 32x64.
// Per (mb,nb): single MMA chain, smalls first, hi*hi LAST (one RZ step with an
// O(1) operand per tile; bias ~2^-24 * sum|tile partial| ~1e-7, audited safe),
// then acc += dl via ONE FADD.RN per element (was two). Pipeline identical to R8.
__global__ void __launch_bounds__(256, 2)
mma_gemm_gelu(const float* __restrict__ A, const __nv_bfloat16* __restrict__ W1,
              const __nv_bfloat16* __restrict__ W2, const __nv_bfloat16* __restrict__ W3,
              const float* __restrict__ bias, float* __restrict__ O, int Kd, int Nn) {
    constexpr int MBLK = 2, NBLK = 8;
    constexpr int APLANE = 128 * 48;     // 6144 B
    constexpr int BPLANE = 128 * 48;
    constexpr int STAGE = 3 * APLANE + 3 * BPLANE;   // 36864 B

    char* smem = g_smem_raw;
    const int tid = threadIdx.x;
    const int lane = tid & 31;
    const int wid = tid >> 5;
    const int wrow = wid >> 1;           // 0..3 -> 32-row strip
    const int wcol = wid & 1;            // 0..1 -> 64-col strip
    const int rowBase = blockIdx.y * 128;
    const int colBase = blockIdx.x * 128;
    const uint32_t sbase = smem_u32(smem);
    const int T = Kd / 16;

    float acc[MBLK][NBLK][4];
#pragma unroll
    for (int mb = 0; mb < MBLK; mb++)
#pragma unroll
        for (int nb = 0; nb < NBLK; nb++)
#pragma unroll
            for (int j = 0; j < 4; j++) acc[mb][nb][j] = 0.0f;

    float4 areg[2];

#define LDG_A(t)                                                                 \
    {                                                                            \
        _Pragma("unroll") for (int i = 0; i < 2; i++) {                          \
            int idx = tid + i * 256;                                             \
            int r = idx >> 2, kq = idx & 3;                                      \
            areg[i] = *reinterpret_cast<const float4*>(                          \
                &A[(size_t)(rowBase + r) * Kd + (t) * 16 + kq * 4]);             \
        }                                                                        \
    }

#define STS_A(s)                                                                 \
    {                                                                            \
        char* dst = smem + (s) * STAGE;                                          \
        _Pragma("unroll") for (int i = 0; i < 2; i++) {                          \
            int idx = tid + i * 256;                                             \
            int r = idx >> 2, kq = idx & 3;                                      \
            float4 v = areg[i];                                                  \
            uint16_t p1[4], p2[4], p3[4];                                        \
            split3(v.x, p1[0], p2[0], p3[0]);                                    \
            split3(v.y, p1[1], p2[1], p3[1]);                                    \
            split3(v.z, p1[2], p2[2], p3[2]);                                    \
            split3(v.w, p1[3], p2[3], p3[3]);                                    \
            int off = r * 48 + kq * 8;                                           \
            uint2 u;                                                             \
            u.x = (uint32_t)p1[0] | ((uint32_t)p1[1] << 16);                     \
            u.y = (uint32_t)p1[2] | ((uint32_t)p1[3] << 16);                     \
            *reinterpret_cast<uint2*>(dst + off) = u;                            \
            u.x = (uint32_t)p2[0] | ((uint32_t)p2[1] << 16);                     \
            u.y = (uint32_t)p2[2] | ((uint32_t)p2[3] << 16);                     \
            *reinterpret_cast<uint2*>(dst + APLANE + off) = u;                   \
            u.x = (uint32_t)p3[0] | ((uint32_t)p3[1] << 16);                     \
            u.y = (uint32_t)p3[2] | ((uint32_t)p3[3] << 16);                     \
            *reinterpret_cast<uint2*>(dst + 2 * APLANE + off) = u;               \
        }                                                                        \
    }

#define CP_B(t, s)                                                               \
    {                                                                            \
        uint32_t bb = sbase + (s) * STAGE + 3 * APLANE;                          \
        _Pragma("unroll") for (int i = 0; i < 3; i++) { /* 768 chunks */         \
            int idx = tid + i * 256;                                             \
            int plane = idx >> 8;                                                \
            int rest = idx & 255;                                                \
            int n = rest >> 1, half = rest & 1;                                  \
            const __nv_bfloat16* src =                                           \
                (plane == 0 ? W1 : plane == 1 ? W2 : W3) +                       \
                (size_t)(colBase + n) * Kd + (t) * 16 + half * 8;                \
            cp_async16(bb + plane * BPLANE + n * 48 + half * 16, src);           \
        }                                                                        \
    }

    // prologue (R8 schedule)
    LDG_A(0);
    CP_B(0, 0);
    CP_COMMIT();
    STS_A(0);
    if (T > 1) LDG_A(1);
    CP_WAIT0();
    __syncthreads();

    const uint32_t aOffL = (uint32_t)((wrow * 32 + (lane & 15)) * 48 + (lane >> 4) * 16);
    const uint32_t bOff4 = (uint32_t)((wcol * 64 + ((lane >> 4) & 1) * 8 + (lane & 7)) * 48 +
                                      ((lane >> 3) & 1) * 16);

    for (int t = 0; t < T; t++) {
        const int s = t & 1;
        if (t + 1 < T) {
            STS_A(s ^ 1);
            CP_B(t + 1, s ^ 1);
            CP_COMMIT();
        }
        if (t + 2 < T) LDG_A(t + 2);

        {
            const uint32_t abase = sbase + s * STAGE;
            const uint32_t bbase = abase + 3 * APLANE;
            uint32_t a[3][MBLK][4];
#pragma unroll
            for (int pa = 0; pa < 3; pa++)
#pragma unroll
                for (int mb = 0; mb < MBLK; mb++)
                    ldsm4(a[pa][mb][0], a[pa][mb][1], a[pa][mb][2], a[pa][mb][3],
                          abase + pa * APLANE + aOffL + mb * 16 * 48);

#pragma unroll
            for (int nb2 = 0; nb2 < 4; nb2++) {
                uint32_t b[3][2][2];
#pragma unroll
                for (int pb = 0; pb < 3; pb++) {
                    uint32_t r0, r1, r2, r3;
                    ldsm4(r0, r1, r2, r3, bbase + pb * BPLANE + bOff4 + nb2 * 16 * 48);
                    b[pb][0][0] = r0; b[pb][0][1] = r1;
                    b[pb][1][0] = r2; b[pb][1][1] = r3;
                }
#pragma unroll
                for (int sub = 0; sub < 2; sub++) {
                    const int nb = nb2 * 2 + sub;
#pragma unroll
                    for (int mb = 0; mb < MBLK; mb++) {
                        float dl[4] = {0.f, 0.f, 0.f, 0.f};
                        mma16(dl, a[1][mb], b[1][sub]);   // mid*mid  (~2^-16)
                        mma16(dl, a[2][mb], b[0][sub]);   // lo*hi    (~2^-16)
                        mma16(dl, a[0][mb], b[2][sub]);   // hi*lo    (~2^-16)
                        mma16(dl, a[1][mb], b[0][sub]);   // mid*hi   (~2^-8)
                        mma16(dl, a[0][mb], b[1][sub]);   // hi*mid   (~2^-8)
                        mma16(dl, a[0][mb], b[0][sub]);   // hi*hi LAST (1 RZ step)
#pragma unroll
                        for (int j = 0; j < 4; j++)
                            acc[mb][nb][j] += dl[j];       // single FADD.RN
                    }
                }
            }
        }
        if (t + 1 < T) CP_WAIT0();
        __syncthreads();
    }
#undef LDG_A
#undef STS_A
#undef CP_B

    // epilogue: bias + gelu, float2 stores (identical to R8)
#pragma unroll
    for (int mb = 0; mb < MBLK; mb++) {
        int r0 = rowBase + wrow * 32 + mb * 16 + (lane >> 2);
#pragma unroll
        for (int nb = 0; nb < NBLK; nb++) {
            int c = colBase + wcol * 64 + nb * 8 + (lane & 3) * 2;
            float b0 = __ldg(&bias[c]);
            float b1 = __ldg(&bias[c + 1]);
            float2 v0, v1;
            v0.x = gelu_tanh(acc[mb][nb][0] + b0);
            v0.y = gelu_tanh(acc[mb][nb][1] + b1);
            v1.x = gelu_tanh(acc[mb][nb][2] + b0);
            v1.y = gelu_tanh(acc[mb][nb][3] + b1);
            *reinterpret_cast<float2*>(&O[(size_t)r0 * Nn + c]) = v0;
            *reinterpret_cast<float2*>(&O[(size_t)(r0 + 8) * Nn + c]) = v1;
        }
    }
}

// ---------------- merged weight transpose + exact bf16x3 split (one launch) ----
__global__ void split_w_all(const float* __restrict__ Wse, const float* __restrict__ W0v,
                            const float* __restrict__ W1v, __nv_bfloat16* __restrict__ o1,
                            __nv_bfloat16* __restrict__ o2, __nv_bfloat16* __restrict__ o3) {
    int i = blockIdx.x * 256 + threadIdx.x;
    if (i >= WSPLIT_TOTAL) return;
    const float* W;
    int K, N, j;
    size_t off;
    if (i < 131072)      { W = Wse; K = 256; N = 512; off = 0;      j = i; }
    else if (i < 393216) { W = W0v; K = 512; N = 512; off = 131072; j = i - 131072; }
    else                 { W = W1v; K = 512; N = 512; off = 393216; j = i - 393216; }
    int k = j / N, n = j - k * N;
    uint16_t s1, s2, s3;
    split3(W[j], s1, s2, s3);
    size_t o = off + (size_t)n * K + k;
    o1[o] = *reinterpret_cast<__nv_bfloat16*>(&s1);
    o2[o] = *reinterpret_cast<__nv_bfloat16*>(&s2);
    o3[o] = *reinterpret_cast<__nv_bfloat16*>(&s3);
}

// ---------------- prep: zero accumulators, code norms ----------------
__global__ void prep_kernel(const float* __restrict__ emb) {
    int gid = blockIdx.x * 1024 + threadIdx.x;
    if (gid < DIM_C * NCODES) g_dw[gid] = 0.0f;
    if (blockIdx.x == 0) {
        int k = threadIdx.x;
        g_counts[k] = 0u;
        float s = 0.0f;
#pragma unroll
        for (int c = 0; c < DIM_C; c++) {
            float v = emb[(size_t)c * NCODES + k];
            s += v * v;
        }
        g_norms[k] = s;
        if (k == 0) g_loss[0] = 0.0f;
    }
}

// ---------------- fused L3 GEMM + VQ (bit-exact fp32 path) ----------------
// phase2 emb tiles double-buffered + cp.async-prefetched (one sync per tile).
#define VQ_AS_F     (128 * 64)
#define VQ_BUF_F    (64 * 64)               // one emb tile, 4096 floats
#define VQ_SMEM_B   ((VQ_AS_F + 2 * VQ_BUF_F) * 4)   // 65536 B

__global__ void __launch_bounds__(256, 2)
vq_fused_kernel(const float* __restrict__ X, const float* __restrict__ w2,
                const float* __restrict__ b2v, const float* __restrict__ emb,
                float* __restrict__ outQ, float* __restrict__ outIdx) {
    constexpr int BM = 128, CD = 64, BN = 64, NT = NCODES / BN;
    float* smem = reinterpret_cast<float*>(g_smem_raw);
    float* As = smem;
    float* At = smem + VQ_AS_F;             // phase1: 32x132 = 4224 floats
    float* Wt = At + 32 * 132;              // phase1: 32x68 = 2176 floats (fits 2 bufs)
    float* buf0 = smem + VQ_AS_F;
    float* buf1 = buf0 + VQ_BUF_F;
    int*   shIdx = reinterpret_cast<int*>(smem + VQ_AS_F);
    float* shRed = smem + VQ_AS_F + 128;

    const int tid = threadIdx.x;
    const int tx = tid & 15;
    const int ty = tid >> 4;
    const int base = blockIdx.x * BM;

    // phase 1: latent = gelu(X @ w2 + b2) (k-ascending fp32x2, bit-exact path)
    {
        unsigned long long acc[8][2];
#pragma unroll
        for (int m = 0; m < 8; m++) { acc[m][0] = 0ull; acc[m][1] = 0ull; }

        for (int kc = 0; kc < DIM_H / 32; kc++) {
#pragma unroll
            for (int i = 0; i < 4; i++) {
                int idx = tid + i * 256;
                int r = idx >> 3, kq = idx & 7;
                float4 v = *reinterpret_cast<const float4*>(
                    &X[(size_t)(base + r) * DIM_H + kc * 32 + kq * 4]);
                At[(kq * 4 + 0) * 132 + r] = v.x;
                At[(kq * 4 + 1) * 132 + r] = v.y;
                At[(kq * 4 + 2) * 132 + r] = v.z;
                At[(kq * 4 + 3) * 132 + r] = v.w;
            }
#pragma unroll
            for (int i = 0; i < 2; i++) {
                int idx = tid + i * 256;
                int krow = idx >> 4, nq = idx & 15;
                *reinterpret_cast<float4*>(&Wt[krow * 68 + nq * 4]) =
                    *reinterpret_cast<const float4*>(
                        &w2[(size_t)(kc * 32 + krow) * DIM_C + nq * 4]);
            }
            __syncthreads();
#pragma unroll 8
            for (int kk = 0; kk < 32; kk++) {
                float4 a0 = *reinterpret_cast<const float4*>(&At[kk * 132 + ty * 8]);
                float4 a1 = *reinterpret_cast<const float4*>(&At[kk * 132 + ty * 8 + 4]);
                float av[8] = {a0.x, a0.y, a0.z, a0.w, a1.x, a1.y, a1.z, a1.w};
                float4 bv = *reinterpret_cast<const float4*>(&Wt[kk * 68 + tx * 4]);
                unsigned long long b20 = pack2(bv.x, bv.y);
                unsigned long long b21 = pack2(bv.z, bv.w);
#pragma unroll
                for (int m = 0; m < 8; m++) {
                    unsigned long long a2 = pack2(av[m], av[m]);
                    acc[m][0] = fma2(a2, b20, acc[m][0]);
                    acc[m][1] = fma2(a2, b21, acc[m][1]);
                }
            }
            __syncthreads();
        }
#pragma unroll
        for (int m = 0; m < 8; m++) {
            int row = ty * 8 + m;
#pragma unroll
            for (int n = 0; n < 2; n++) {
                int col = tx * 4 + n * 2;
                float2 v = unpack2(acc[m][n]);
                float2 o;
                o.x = gelu_tanh(v.x + b2v[col]);
                o.y = gelu_tanh(v.y + b2v[col + 1]);
                *reinterpret_cast<float2*>(&As[row * CD + col]) = o;
            }
        }
    }
    __syncthreads();

    // phase 2: VQ with double-buffered emb tiles
    float best[8];
    int bidx[8];
#pragma unroll
    for (int m = 0; m < 8; m++) { best[m] = -3.4e38f; bidx[m] = 0; }

    const uint32_t buf0a = smem_u32(buf0);
    const uint32_t buf1a = smem_u32(buf1);

#define CP_EMB(t, bufaddr)                                                       \
    {                                                                            \
        _Pragma("unroll") for (int it = 0; it < 4; it++) {                       \
            int idx = tid + it * 256;                                            \
            int c = idx >> 4;                                                    \
            int jq = idx & 15;                                                   \
            cp_async16((bufaddr) + (uint32_t)(c * BN + jq * 4) * 4,              \
                       &emb[(size_t)c * NCODES + (t) * BN + jq * 4]);            \
        }                                                                        \
    }

    CP_EMB(0, buf0a);
    CP_COMMIT();
    CP_WAIT0();
    __syncthreads();

    for (int t = 0; t < NT; t++) {
        const float* cur = (t & 1) ? buf1 : buf0;
        if (t + 1 < NT) {
            CP_EMB(t + 1, (t & 1) ? buf0a : buf1a);
            CP_COMMIT();
        }

        unsigned long long acc[8][2];
#pragma unroll
        for (int m = 0; m < 8; m++) { acc[m][0] = 0ull; acc[m][1] = 0ull; }

#pragma unroll 4
        for (int c = 0; c < CD; c++) {
            float4 bv = *reinterpret_cast<const float4*>(&cur[c * BN + tx * 4]);
            unsigned long long b20 = pack2(bv.x, bv.y);
            unsigned long long b21 = pack2(bv.z, bv.w);
#pragma unroll
            for (int m = 0; m < 8; m++) {
                float a = As[(ty * 8 + m) * CD + c];
                unsigned long long a2 = pack2(a, a);
                acc[m][0] = fma2(a2, b20, acc[m][0]);
                acc[m][1] = fma2(a2, b21, acc[m][1]);
            }
        }

        int cbase = t * BN + tx * 4;
        float n0 = __ldg(&g_norms[cbase + 0]);
        float n1 = __ldg(&g_norms[cbase + 1]);
        float n2 = __ldg(&g_norms[cbase + 2]);
        float n3 = __ldg(&g_norms[cbase + 3]);
#pragma unroll
        for (int m = 0; m < 8; m++) {
            float2 s0 = unpack2(acc[m][0]);
            float2 s1 = unpack2(acc[m][1]);
            float sc;
            sc = 2.0f * s0.x - n0; if (sc > best[m]) { best[m] = sc; bidx[m] = cbase + 0; }
            sc = 2.0f * s0.y - n1; if (sc > best[m]) { best[m] = sc; bidx[m] = cbase + 1; }
            sc = 2.0f * s1.x - n2; if (sc > best[m]) { best[m] = sc; bidx[m] = cbase + 2; }
            sc = 2.0f * s1.y - n3; if (sc > best[m]) { best[m] = sc; bidx[m] = cbase + 3; }
        }
        if (t + 1 < NT) CP_WAIT0();
        __syncthreads();
    }
#undef CP_EMB

#pragma unroll
    for (int m = 0; m < 8; m++) {
#pragma unroll
        for (int off = 8; off > 0; off >>= 1) {
            float ob = __shfl_xor_sync(0xffffffffu, best[m], off);
            int oi = __shfl_xor_sync(0xffffffffu, bidx[m], off);
            if (ob > best[m] || (ob == best[m] && oi < bidx[m])) { best[m] = ob; bidx[m] = oi; }
        }
    }
    __syncthreads();
    if (tx == 0) {
#pragma unroll
        for (int m = 0; m < 8; m++) shIdx[ty * 8 + m] = bidx[m];
    }
    __syncthreads();

    if (tid < BM) {
        int id = shIdx[tid];
        outIdx[base + tid] = (float)id;
        atomicAdd(&g_counts[id], 1u);
    }
    float lsum = 0.0f;
#pragma unroll 8
    for (int it = 0; it < 32; it++) {
        int i = tid + it * 256;
        int row = i >> 6;
        int c = i & 63;
        int id = shIdx[row];
        float l = As[row * CD + c];
        float q = __ldg(&emb[(size_t)c * NCODES + id]);
        outQ[(size_t)(base + row) * CD + c] = l + (q - l);
        float d = q - l;
        lsum += d * d;
        atomicAdd(&g_dw[(size_t)c * NCODES + id], l);
    }
    shRed[tid] = lsum;
    __syncthreads();
    for (int s = 128; s > 0; s >>= 1) {
        if (tid < s) shRed[tid] += shRed[tid + s];
        __syncthreads();
    }
    if (tid == 0) atomicAdd(&g_loss[0], shRed[0]);
}

// ---------------- finalize ----------------
__global__ void __launch_bounds__(1024)
finalize_kernel(const float* __restrict__ ema_cluster,
                const float* __restrict__ ema_dw,
                float* __restrict__ out) {
    constexpr size_t LOSS_OFF = (size_t)NTOK * DIM_C;
    constexpr size_t PERP_OFF = LOSS_OFF + 1;
    constexpr size_t IDX_OFF = PERP_OFF + 1;
    constexpr size_t EMB_OFF = IDX_OFF + (size_t)NTOK;

    __shared__ float red[1024];
    int k = threadIdx.x;
    float debias = (float)(1.0 - pow(0.99, 1001.0));

    float cnt = (float)g_counts[k];
    float clh = ema_cluster[k] * DECAY_F + cnt * (1.0f - DECAY_F);
    float cs = clh / debias;

    red[k] = cs;
    __syncthreads();
    for (int s = 512; s > 0; s >>= 1) {
        if (k < s) red[k] += red[k + s];
        __syncthreads();
    }
    float n = red[0];
    __syncthreads();

    float p = cnt / (float)NTOK;
    red[k] = p * logf(p + 1e-10f);
    __syncthreads();
    for (int s = 512; s > 0; s >>= 1) {
        if (k < s) red[k] += red[k + s];
        __syncthreads();
    }
    float pl = red[0];

    float stable = (cs + 1e-5f) / (n + (float)NCODES * 1e-5f) * n;
#pragma unroll 4
    for (int c = 0; c < DIM_C; c++) {
        size_t i = (size_t)c * NCODES + k;
        float upd = (ema_dw[i] * DECAY_F + g_dw[i] * (1.0f - DECAY_F)) / debias;
        out[EMB_OFF + i] = upd / stable;
    }
    if (k == 0) {
        out[LOSS_OFF] = 0.25f * (g_loss[0] / ((float)NTOK * (float)DIM_C));
        out[PERP_OFF] = expf(-pl);
    }
}

// ---------------- launch ----------------
extern "C" void kernel_launch(void* const* d_in, const int* in_sizes, int n_in,
                              void* d_out, int out_size) {
    const float* states = (const float*)d_in[0];
    const float* w_se = (const float*)d_in[1];
    const float* b_se = (const float*)d_in[2];
    const float* w0 = (const float*)d_in[3];
    const float* b0 = (const float*)d_in[4];
    const float* w1 = (const float*)d_in[5];
    const float* b1 = (const float*)d_in[6];
    const float* w2 = (const float*)d_in[7];
    const float* b2 = (const float*)d_in[8];
    const float* emb = (const float*)d_in[9];
    const float* ema_cluster = (const float*)d_in[10];
    const float* ema_dw = (const float*)d_in[11];
    float* out = (float*)d_out;

    float *bufA, *bufB;
    __nv_bfloat16 *wb1, *wb2, *wb3;
    cudaGetSymbolAddress((void**)&bufA, g_bufA);
    cudaGetSymbolAddress((void**)&bufB, g_bufB);
    cudaGetSymbolAddress((void**)&wb1, g_wb1);
    cudaGetSymbolAddress((void**)&wb2, g_wb2);
    cudaGetSymbolAddress((void**)&wb3, g_wb3);

    const size_t IDX_OFF = (size_t)NTOK * DIM_C + 2;

    const int MMA_SMEM = 2 * (3 * 128 * 48 + 3 * 128 * 48);  // 73728 (2 stages, R8)
    cudaFuncSetAttribute(mma_gemm_gelu,
                         cudaFuncAttributeMaxDynamicSharedMemorySize, MMA_SMEM);
    cudaFuncSetAttribute(vq_fused_kernel,
                         cudaFuncAttributeMaxDynamicSharedMemorySize, VQ_SMEM_B);

    // merged weight split + prep
    split_w_all<<<(WSPLIT_TOTAL + 255) / 256, 256>>>(w_se, w0, w1, wb1, wb2, wb3);
    prep_kernel<<<64, 1024>>>(emb);

    dim3 blk(256);
    mma_gemm_gelu<<<dim3(DIM_E / 128, NTOK / 128), blk, MMA_SMEM>>>(
        states, wb1, wb2, wb3, b_se, bufA, DIM_D, DIM_E);
    mma_gemm_gelu<<<dim3(DIM_H / 128, NTOK / 128), blk, MMA_SMEM>>>(
        bufA, wb1 + 131072, wb2 + 131072, wb3 + 131072, b0, bufB, DIM_E, DIM_H);
    mma_gemm_gelu<<<dim3(DIM_H / 128, NTOK / 128), blk, MMA_SMEM>>>(
        bufB, wb1 + 393216, wb2 + 393216, wb3 + 393216, b1, bufA, DIM_H, DIM_H);

    vq_fused_kernel<<<NTOK / 128, blk, VQ_SMEM_B>>>(
        bufA, w2, b2, emb, out /*quantized*/, out + IDX_OFF);
    finalize_kernel<<<1, 1024>>>(ema_cluster, ema_dw, out);
}

// round 14
// speedup vs baseline: 1.2256x; 1.0066x over previous
#include <cuda_runtime.h>
#include <cuda_bf16.h>
#include <cstdint>
#include <cstddef>

// ---------------- problem constants ----------------
#define NTOK   98304      // 32768 * 3 tokens
#define DIM_D  256
#define DIM_E  512
#define DIM_H  512
#define DIM_C  64
#define NCODES 1024
#define DECAY_F 0.99f

// single extern shared decl (consistent type across all kernels)
extern __shared__ __align__(16) char g_smem_raw[];

// ---------------- scratch (device globals; no allocs allowed) ----------------
__device__ float g_bufA[NTOK * DIM_E];
__device__ float g_bufB[NTOK * DIM_H];
__device__ float g_dw[DIM_C * NCODES];
__device__ unsigned int g_counts[NCODES];
__device__ float g_norms[NCODES];
__device__ float g_loss[1];

// weights (L0..L3) pre-split into 3 bf16 planes, transposed [N,K] K-major
// offsets: L0 (N=512,K=256)=0, L1=131072, L2=393216, L3 (N=64,K=512)=655360
#define WSPLIT_TOTAL 688128
__device__ __nv_bfloat16 g_wb1[WSPLIT_TOTAL];
__device__ __nv_bfloat16 g_wb2[WSPLIT_TOTAL];
__device__ __nv_bfloat16 g_wb3[WSPLIT_TOTAL];

// ---------------- small helpers ----------------
__device__ __forceinline__ uint32_t smem_u32(const void* p) {
    uint32_t a;
    asm("{ .reg .u64 t; cvta.to.shared.u64 t, %1; cvt.u32.u64 %0, t; }"
        : "=r"(a) : "l"(p));
    return a;
}
__device__ __forceinline__ float gelu_tanh(float x) {
    float x3 = x * x * x;
    float t = tanhf(0.7978845608028654f * (x + 0.044715f * x3));
    return 0.5f * x * (1.0f + t);
}
__device__ __forceinline__ void cp_async16(uint32_t saddr, const void* gptr) {
    asm volatile("cp.async.ca.shared.global [%0], [%1], 16;"
                 :: "r"(saddr), "l"(gptr) : "memory");
}
#define CP_COMMIT() asm volatile("cp.async.commit_group;" ::: "memory")
#define CP_WAIT0()  asm volatile("cp.async.wait_group 0;" ::: "memory")

// exact 3-way bf16 split of fp32 (24 = 8+8+8 mantissa bits)
__device__ __forceinline__ void split3(float x, uint16_t& s1, uint16_t& s2, uint16_t& s3) {
    __nv_bfloat16 b1 = __float2bfloat16_rn(x);
    float r = x - __bfloat162float(b1);
    __nv_bfloat16 b2 = __float2bfloat16_rn(r);
    float r2 = r - __bfloat162float(b2);
    __nv_bfloat16 b3 = __float2bfloat16_rn(r2);
    s1 = *reinterpret_cast<uint16_t*>(&b1);
    s2 = *reinterpret_cast<uint16_t*>(&b2);
    s3 = *reinterpret_cast<uint16_t*>(&b3);
}

__device__ __forceinline__ void ldsm4(uint32_t& r0, uint32_t& r1, uint32_t& r2,
                                      uint32_t& r3, uint32_t addr) {
    asm volatile("ldmatrix.sync.aligned.m8n8.x4.shared.b16 {%0,%1,%2,%3}, [%4];"
                 : "=r"(r0), "=r"(r1), "=r"(r2), "=r"(r3) : "r"(addr));
}
__device__ __forceinline__ void mma16(float* c, const uint32_t* a, const uint32_t* b) {
    asm volatile(
        "mma.sync.aligned.m16n8k16.row.col.f32.bf16.bf16.f32 "
        "{%0,%1,%2,%3}, {%4,%5,%6,%7}, {%8,%9}, {%0,%1,%2,%3};"
        : "+f"(c[0]), "+f"(c[1]), "+f"(c[2]), "+f"(c[3])
        : "r"(a[0]), "r"(a[1]), "r"(a[2]), "r"(a[3]), "r"(b[0]), "r"(b[1]));
}

// f32x2 packed helpers (vq phase 2)
__device__ __forceinline__ unsigned long long pack2(float lo, float hi) {
    unsigned long long r;
    asm("mov.b64 %0, {%1, %2};" : "=l"(r) : "f"(lo), "f"(hi));
    return r;
}
__device__ __forceinline__ unsigned long long fma2(unsigned long long a,
                                                   unsigned long long b,
                                                   unsigned long long c) {
    unsigned long long d;
    asm("fma.rn.f32x2 %0, %1, %2, %3;" : "=l"(d) : "l"(a), "l"(b), "l"(c));
    return d;
}
__device__ __forceinline__ float2 unpack2(unsigned long long v) {
    float lo, hi;
    asm("mov.b64 {%0, %1}, %2;" : "=f"(lo), "=f"(hi) : "l"(v));
    return make_float2(lo, hi);
}

// ---------------- bf16x3 six-pass GEMM, merged-chain fold (R13, WIN baseline) --
__global__ void __launch_bounds__(256, 2)
mma_gemm_gelu(const float* __restrict__ A, const __nv_bfloat16* __restrict__ W1,
              const __nv_bfloat16* __restrict__ W2, const __nv_bfloat16* __restrict__ W3,
              const float* __restrict__ bias, float* __restrict__ O, int Kd, int Nn) {
    constexpr int MBLK = 2, NBLK = 8;
    constexpr int APLANE = 128 * 48;
    constexpr int BPLANE = 128 * 48;
    constexpr int STAGE = 3 * APLANE + 3 * BPLANE;   // 36864 B

    char* smem = g_smem_raw;
    const int tid = threadIdx.x;
    const int lane = tid & 31;
    const int wid = tid >> 5;
    const int wrow = wid >> 1;
    const int wcol = wid & 1;
    const int rowBase = blockIdx.y * 128;
    const int colBase = blockIdx.x * 128;
    const uint32_t sbase = smem_u32(smem);
    const int T = Kd / 16;

    float acc[MBLK][NBLK][4];
#pragma unroll
    for (int mb = 0; mb < MBLK; mb++)
#pragma unroll
        for (int nb = 0; nb < NBLK; nb++)
#pragma unroll
            for (int j = 0; j < 4; j++) acc[mb][nb][j] = 0.0f;

    float4 areg[2];

#define LDG_A(t)                                                                 \
    {                                                                            \
        _Pragma("unroll") for (int i = 0; i < 2; i++) {                          \
            int idx = tid + i * 256;                                             \
            int r = idx >> 2, kq = idx & 3;                                      \
            areg[i] = *reinterpret_cast<const float4*>(                          \
                &A[(size_t)(rowBase + r) * Kd + (t) * 16 + kq * 4]);             \
        }                                                                        \
    }

#define STS_A(s)                                                                 \
    {                                                                            \
        char* dst = smem + (s) * STAGE;                                          \
        _Pragma("unroll") for (int i = 0; i < 2; i++) {                          \
            int idx = tid + i * 256;                                             \
            int r = idx >> 2, kq = idx & 3;                                      \
            float4 v = areg[i];                                                  \
            uint16_t p1[4], p2[4], p3[4];                                        \
            split3(v.x, p1[0], p2[0], p3[0]);                                    \
            split3(v.y, p1[1], p2[1], p3[1]);                                    \
            split3(v.z, p1[2], p2[2], p3[2]);                                    \
            split3(v.w, p1[3], p2[3], p3[3]);                                    \
            int off = r * 48 + kq * 8;                                           \
            uint2 u;                                                             \
            u.x = (uint32_t)p1[0] | ((uint32_t)p1[1] << 16);                     \
            u.y = (uint32_t)p1[2] | ((uint32_t)p1[3] << 16);                     \
            *reinterpret_cast<uint2*>(dst + off) = u;                            \
            u.x = (uint32_t)p2[0] | ((uint32_t)p2[1] << 16);                     \
            u.y = (uint32_t)p2[2] | ((uint32_t)p2[3] << 16);                     \
            *reinterpret_cast<uint2*>(dst + APLANE + off) = u;                   \
            u.x = (uint32_t)p3[0] | ((uint32_t)p3[1] << 16);                     \
            u.y = (uint32_t)p3[2] | ((uint32_t)p3[3] << 16);                     \
            *reinterpret_cast<uint2*>(dst + 2 * APLANE + off) = u;               \
        }                                                                        \
    }

#define CP_B(t, s)                                                               \
    {                                                                            \
        uint32_t bb = sbase + (s) * STAGE + 3 * APLANE;                          \
        _Pragma("unroll") for (int i = 0; i < 3; i++) {                          \
            int idx = tid + i * 256;                                             \
            int plane = idx >> 8;                                                \
            int rest = idx & 255;                                                \
            int n = rest >> 1, half = rest & 1;                                  \
            const __nv_bfloat16* src =                                           \
                (plane == 0 ? W1 : plane == 1 ? W2 : W3) +                       \
                (size_t)(colBase + n) * Kd + (t) * 16 + half * 8;                \
            cp_async16(bb + plane * BPLANE + n * 48 + half * 16, src);           \
        }                                                                        \
    }

    LDG_A(0);
    CP_B(0, 0);
    CP_COMMIT();
    STS_A(0);
    if (T > 1) LDG_A(1);
    CP_WAIT0();
    __syncthreads();

    const uint32_t aOffL = (uint32_t)((wrow * 32 + (lane & 15)) * 48 + (lane >> 4) * 16);
    const uint32_t bOff4 = (uint32_t)((wcol * 64 + ((lane >> 4) & 1) * 8 + (lane & 7)) * 48 +
                                      ((lane >> 3) & 1) * 16);

    for (int t = 0; t < T; t++) {
        const int s = t & 1;
        if (t + 1 < T) {
            STS_A(s ^ 1);
            CP_B(t + 1, s ^ 1);
            CP_COMMIT();
        }
        if (t + 2 < T) LDG_A(t + 2);

        {
            const uint32_t abase = sbase + s * STAGE;
            const uint32_t bbase = abase + 3 * APLANE;
            uint32_t a[3][MBLK][4];
#pragma unroll
            for (int pa = 0; pa < 3; pa++)
#pragma unroll
                for (int mb = 0; mb < MBLK; mb++)
                    ldsm4(a[pa][mb][0], a[pa][mb][1], a[pa][mb][2], a[pa][mb][3],
                          abase + pa * APLANE + aOffL + mb * 16 * 48);

#pragma unroll
            for (int nb2 = 0; nb2 < 4; nb2++) {
                uint32_t b[3][2][2];
#pragma unroll
                for (int pb = 0; pb < 3; pb++) {
                    uint32_t r0, r1, r2, r3;
                    ldsm4(r0, r1, r2, r3, bbase + pb * BPLANE + bOff4 + nb2 * 16 * 48);
                    b[pb][0][0] = r0; b[pb][0][1] = r1;
                    b[pb][1][0] = r2; b[pb][1][1] = r3;
                }
#pragma unroll
                for (int sub = 0; sub < 2; sub++) {
                    const int nb = nb2 * 2 + sub;
#pragma unroll
                    for (int mb = 0; mb < MBLK; mb++) {
                        float dl[4] = {0.f, 0.f, 0.f, 0.f};
                        mma16(dl, a[1][mb], b[1][sub]);   // mid*mid
                        mma16(dl, a[2][mb], b[0][sub]);   // lo*hi
                        mma16(dl, a[0][mb], b[2][sub]);   // hi*lo
                        mma16(dl, a[1][mb], b[0][sub]);   // mid*hi
                        mma16(dl, a[0][mb], b[1][sub]);   // hi*mid
                        mma16(dl, a[0][mb], b[0][sub]);   // hi*hi LAST
#pragma unroll
                        for (int j = 0; j < 4; j++)
                            acc[mb][nb][j] += dl[j];       // single FADD.RN
                    }
                }
            }
        }
        if (t + 1 < T) CP_WAIT0();
        __syncthreads();
    }
#undef LDG_A
#undef STS_A
#undef CP_B

#pragma unroll
    for (int mb = 0; mb < MBLK; mb++) {
        int r0 = rowBase + wrow * 32 + mb * 16 + (lane >> 2);
#pragma unroll
        for (int nb = 0; nb < NBLK; nb++) {
            int c = colBase + wcol * 64 + nb * 8 + (lane & 3) * 2;
            float b0 = __ldg(&bias[c]);
            float b1 = __ldg(&bias[c + 1]);
            float2 v0, v1;
            v0.x = gelu_tanh(acc[mb][nb][0] + b0);
            v0.y = gelu_tanh(acc[mb][nb][1] + b1);
            v1.x = gelu_tanh(acc[mb][nb][2] + b0);
            v1.y = gelu_tanh(acc[mb][nb][3] + b1);
            *reinterpret_cast<float2*>(&O[(size_t)r0 * Nn + c]) = v0;
            *reinterpret_cast<float2*>(&O[(size_t)(r0 + 8) * Nn + c]) = v1;
        }
    }
}

// ---------------- merged weight transpose + exact bf16x3 split (L0..L3) --------
__global__ void split_w_all(const float* __restrict__ Wse, const float* __restrict__ W0v,
                            const float* __restrict__ W1v, const float* __restrict__ W2v,
                            __nv_bfloat16* __restrict__ o1, __nv_bfloat16* __restrict__ o2,
                            __nv_bfloat16* __restrict__ o3) {
    int i = blockIdx.x * 256 + threadIdx.x;
    if (i >= WSPLIT_TOTAL) return;
    const float* W;
    int K, N, j;
    size_t off;
    if (i < 131072)      { W = Wse; K = 256; N = 512; off = 0;      j = i; }
    else if (i < 393216) { W = W0v; K = 512; N = 512; off = 131072; j = i - 131072; }
    else if (i < 655360) { W = W1v; K = 512; N = 512; off = 393216; j = i - 393216; }
    else                 { W = W2v; K = 512; N = 64;  off = 655360; j = i - 655360; }
    int k = j / N, n = j - k * N;
    uint16_t s1, s2, s3;
    split3(W[j], s1, s2, s3);
    size_t o = off + (size_t)n * K + k;
    o1[o] = *reinterpret_cast<__nv_bfloat16*>(&s1);
    o2[o] = *reinterpret_cast<__nv_bfloat16*>(&s2);
    o3[o] = *reinterpret_cast<__nv_bfloat16*>(&s3);
}

// ---------------- prep: zero accumulators, code norms ----------------
__global__ void prep_kernel(const float* __restrict__ emb) {
    int gid = blockIdx.x * 1024 + threadIdx.x;
    if (gid < DIM_C * NCODES) g_dw[gid] = 0.0f;
    if (blockIdx.x == 0) {
        int k = threadIdx.x;
        g_counts[k] = 0u;
        float s = 0.0f;
#pragma unroll
        for (int c = 0; c < DIM_C; c++) {
            float v = emb[(size_t)c * NCODES + k];
            s += v * v;
        }
        g_norms[k] = s;
        if (k == 0) g_loss[0] = 0.0f;
    }
}

// ---------------- fused L3(MMA) + VQ ----------------
// Phase 1: latent[128,64] = gelu(X[128,512] @ w2 + b2) via the PROVEN bf16x3
//          merged-chain MMA scheme (BN=64, warp tile 32x32, T=32).
// Phase 2: fp32 distances + argmax with double-buffered emb tiles (R13).
#define VQ_AS_B     (128 * 64 * 4)          // 32768 B latent region
#define VQ_APLANE   (128 * 48)              // 6144
#define VQ_BPLANE   (64 * 48)               // 3072
#define VQ_STAGE    (3 * VQ_APLANE + 3 * VQ_BPLANE)   // 27648
#define VQ_SMEM_B   (VQ_AS_B + 2 * VQ_STAGE)          // 88064

__global__ void __launch_bounds__(256, 2)
vq_fused_kernel(const float* __restrict__ X, const __nv_bfloat16* __restrict__ W1,
                const __nv_bfloat16* __restrict__ W2, const __nv_bfloat16* __restrict__ W3,
                const float* __restrict__ b2v, const float* __restrict__ emb,
                float* __restrict__ outQ, float* __restrict__ outIdx) {
    constexpr int BM = 128, CD = 64, BN = 64, NT = NCODES / BN;
    char* smemc = g_smem_raw;
    float* As = reinterpret_cast<float*>(smemc);                  // latent [128][64]
    float* buf0 = reinterpret_cast<float*>(smemc + VQ_AS_B);      // phase2 emb bufs
    float* buf1 = buf0 + 64 * 64;
    int*   shIdx = reinterpret_cast<int*>(smemc + VQ_AS_B);
    float* shRed = reinterpret_cast<float*>(smemc + VQ_AS_B) + 128;

    const int tid = threadIdx.x;
    const int lane = tid & 31;
    const int wid = tid >> 5;
    const int wrow = wid >> 1;           // 0..3 -> 32-row strip
    const int wcol = wid & 1;            // 0..1 -> 32-col strip
    const int tx = tid & 15;
    const int ty = tid >> 4;
    const int base = blockIdx.x * BM;
    const uint32_t sbase = smem_u32(smemc);
    constexpr int T = DIM_H / 16;        // 32

    // ---- phase 1: latent via bf16x3 MMA ----
    {
        float acc[2][4][4];
#pragma unroll
        for (int mb = 0; mb < 2; mb++)
#pragma unroll
            for (int nb = 0; nb < 4; nb++)
#pragma unroll
                for (int j = 0; j < 4; j++) acc[mb][nb][j] = 0.0f;

        float4 areg[2];

#define VLDG_A(t)                                                                \
    {                                                                            \
        _Pragma("unroll") for (int i = 0; i < 2; i++) {                          \
            int idx = tid + i * 256;                                             \
            int r = idx >> 2, kq = idx & 3;                                      \
            areg[i] = *reinterpret_cast<const float4*>(                          \
                &X[(size_t)(base + r) * DIM_H + (t) * 16 + kq * 4]);             \
        }                                                                        \
    }

#define VSTS_A(s)                                                                \
    {                                                                            \
        char* dst = smemc + VQ_AS_B + (s) * VQ_STAGE;                            \
        _Pragma("unroll") for (int i = 0; i < 2; i++) {                          \
            int idx = tid + i * 256;                                             \
            int r = idx >> 2, kq = idx & 3;                                      \
            float4 v = areg[i];                                                  \
            uint16_t p1[4], p2[4], p3[4];                                        \
            split3(v.x, p1[0], p2[0], p3[0]);                                    \
            split3(v.y, p1[1], p2[1], p3[1]);                                    \
            split3(v.z, p1[2], p2[2], p3[2]);                                    \
            split3(v.w, p1[3], p2[3], p3[3]);                                    \
            int off = r * 48 + kq * 8;                                           \
            uint2 u;                                                             \
            u.x = (uint32_t)p1[0] | ((uint32_t)p1[1] << 16);                     \
            u.y = (uint32_t)p1[2] | ((uint32_t)p1[3] << 16);                     \
            *reinterpret_cast<uint2*>(dst + off) = u;                            \
            u.x = (uint32_t)p2[0] | ((uint32_t)p2[1] << 16);                     \
            u.y = (uint32_t)p2[2] | ((uint32_t)p2[3] << 16);                     \
            *reinterpret_cast<uint2*>(dst + VQ_APLANE + off) = u;                \
            u.x = (uint32_t)p3[0] | ((uint32_t)p3[1] << 16);                     \
            u.y = (uint32_t)p3[2] | ((uint32_t)p3[3] << 16);                     \
            *reinterpret_cast<uint2*>(dst + 2 * VQ_APLANE + off) = u;            \
        }                                                                        \
    }

#define VCP_B(t, s)                                                              \
    {                                                                            \
        uint32_t bb = sbase + VQ_AS_B + (s) * VQ_STAGE + 3 * VQ_APLANE;          \
        _Pragma("unroll") for (int i = 0; i < 2; i++) { /* 384 chunks */         \
            int idx = tid + i * 256;                                             \
            if (idx < 384) {                                                     \
                int plane = idx >> 7;                                            \
                int rest = idx & 127;                                            \
                int n = rest >> 1, half = rest & 1;                              \
                const __nv_bfloat16* src =                                       \
                    (plane == 0 ? W1 : plane == 1 ? W2 : W3) +                   \
                    (size_t)n * DIM_H + (t) * 16 + half * 8;                     \
                cp_async16(bb + plane * VQ_BPLANE + n * 48 + half * 16, src);    \
            }                                                                    \
        }                                                                        \
    }

        VLDG_A(0);
        VCP_B(0, 0);
        CP_COMMIT();
        VSTS_A(0);
        VLDG_A(1);
        CP_WAIT0();
        __syncthreads();

        const uint32_t aOffL = (uint32_t)((wrow * 32 + (lane & 15)) * 48 + (lane >> 4) * 16);
        const uint32_t bOffV = (uint32_t)((wcol * 32 + ((lane >> 4) & 1) * 8 + (lane & 7)) * 48 +
                                          ((lane >> 3) & 1) * 16);

        for (int t = 0; t < T; t++) {
            const int s = t & 1;
            if (t + 1 < T) {
                VSTS_A(s ^ 1);
                VCP_B(t + 1, s ^ 1);
                CP_COMMIT();
            }
            if (t + 2 < T) VLDG_A(t + 2);

            {
                const uint32_t abase = sbase + VQ_AS_B + s * VQ_STAGE;
                const uint32_t bbase = abase + 3 * VQ_APLANE;
                uint32_t a[3][2][4];
#pragma unroll
                for (int pa = 0; pa < 3; pa++)
#pragma unroll
                    for (int mb = 0; mb < 2; mb++)
                        ldsm4(a[pa][mb][0], a[pa][mb][1], a[pa][mb][2], a[pa][mb][3],
                              abase + pa * VQ_APLANE + aOffL + mb * 16 * 48);

#pragma unroll
                for (int nb2 = 0; nb2 < 2; nb2++) {
                    uint32_t b[3][2][2];
#pragma unroll
                    for (int pb = 0; pb < 3; pb++) {
                        uint32_t r0, r1, r2, r3;
                        ldsm4(r0, r1, r2, r3,
                              bbase + pb * VQ_BPLANE + bOffV + nb2 * 16 * 48);
                        b[pb][0][0] = r0; b[pb][0][1] = r1;
                        b[pb][1][0] = r2; b[pb][1][1] = r3;
                    }
#pragma unroll
                    for (int sub = 0; sub < 2; sub++) {
                        const int nb = nb2 * 2 + sub;
#pragma unroll
                        for (int mb = 0; mb < 2; mb++) {
                            float dl[4] = {0.f, 0.f, 0.f, 0.f};
                            mma16(dl, a[1][mb], b[1][sub]);
                            mma16(dl, a[2][mb], b[0][sub]);
                            mma16(dl, a[0][mb], b[2][sub]);
                            mma16(dl, a[1][mb], b[0][sub]);
                            mma16(dl, a[0][mb], b[1][sub]);
                            mma16(dl, a[0][mb], b[0][sub]);   // hi*hi last
#pragma unroll
                            for (int j = 0; j < 4; j++) acc[mb][nb][j] += dl[j];
                        }
                    }
                }
            }
            if (t + 1 < T) CP_WAIT0();
            __syncthreads();
        }
#undef VLDG_A
#undef VSTS_A
#undef VCP_B

        // epilogue: bias + gelu -> latent smem As
#pragma unroll
        for (int mb = 0; mb < 2; mb++) {
            int r0 = wrow * 32 + mb * 16 + (lane >> 2);
#pragma unroll
            for (int nb = 0; nb < 4; nb++) {
                int c = wcol * 32 + nb * 8 + (lane & 3) * 2;
                float b0 = __ldg(&b2v[c]);
                float b1 = __ldg(&b2v[c + 1]);
                float2 v0, v1;
                v0.x = gelu_tanh(acc[mb][nb][0] + b0);
                v0.y = gelu_tanh(acc[mb][nb][1] + b1);
                v1.x = gelu_tanh(acc[mb][nb][2] + b0);
                v1.y = gelu_tanh(acc[mb][nb][3] + b1);
                *reinterpret_cast<float2*>(&As[r0 * CD + c]) = v0;
                *reinterpret_cast<float2*>(&As[(r0 + 8) * CD + c]) = v1;
            }
        }
    }
    __syncthreads();

    // ---- phase 2: VQ with double-buffered emb tiles (fp32 exact) ----
    float best[8];
    int bidx[8];
#pragma unroll
    for (int m = 0; m < 8; m++) { best[m] = -3.4e38f; bidx[m] = 0; }

    const uint32_t buf0a = smem_u32(buf0);
    const uint32_t buf1a = smem_u32(buf1);

#define CP_EMB(t, bufaddr)                                                       \
    {                                                                            \
        _Pragma("unroll") for (int it = 0; it < 4; it++) {                       \
            int idx = tid + it * 256;                                            \
            int c = idx >> 4;                                                    \
            int jq = idx & 15;                                                   \
            cp_async16((bufaddr) + (uint32_t)(c * BN + jq * 4) * 4,              \
                       &emb[(size_t)c * NCODES + (t) * BN + jq * 4]);            \
        }                                                                        \
    }

    CP_EMB(0, buf0a);
    CP_COMMIT();
    CP_WAIT0();
    __syncthreads();

    for (int t = 0; t < NT; t++) {
        const float* cur = (t & 1) ? buf1 : buf0;
        if (t + 1 < NT) {
            CP_EMB(t + 1, (t & 1) ? buf0a : buf1a);
            CP_COMMIT();
        }

        unsigned long long acc[8][2];
#pragma unroll
        for (int m = 0; m < 8; m++) { acc[m][0] = 0ull; acc[m][1] = 0ull; }

#pragma unroll 4
        for (int c = 0; c < CD; c++) {
            float4 bv = *reinterpret_cast<const float4*>(&cur[c * BN + tx * 4]);
            unsigned long long b20 = pack2(bv.x, bv.y);
            unsigned long long b21 = pack2(bv.z, bv.w);
#pragma unroll
            for (int m = 0; m < 8; m++) {
                float a = As[(ty * 8 + m) * CD + c];
                unsigned long long a2 = pack2(a, a);
                acc[m][0] = fma2(a2, b20, acc[m][0]);
                acc[m][1] = fma2(a2, b21, acc[m][1]);
            }
        }

        int cbase = t * BN + tx * 4;
        float n0 = __ldg(&g_norms[cbase + 0]);
        float n1 = __ldg(&g_norms[cbase + 1]);
        float n2 = __ldg(&g_norms[cbase + 2]);
        float n3 = __ldg(&g_norms[cbase + 3]);
#pragma unroll
        for (int m = 0; m < 8; m++) {
            float2 s0 = unpack2(acc[m][0]);
            float2 s1 = unpack2(acc[m][1]);
            float sc;
            sc = 2.0f * s0.x - n0; if (sc > best[m]) { best[m] = sc; bidx[m] = cbase + 0; }
            sc = 2.0f * s0.y - n1; if (sc > best[m]) { best[m] = sc; bidx[m] = cbase + 1; }
            sc = 2.0f * s1.x - n2; if (sc > best[m]) { best[m] = sc; bidx[m] = cbase + 2; }
            sc = 2.0f * s1.y - n3; if (sc > best[m]) { best[m] = sc; bidx[m] = cbase + 3; }
        }
        if (t + 1 < NT) CP_WAIT0();
        __syncthreads();
    }
#undef CP_EMB

#pragma unroll
    for (int m = 0; m < 8; m++) {
#pragma unroll
        for (int off = 8; off > 0; off >>= 1) {
            float ob = __shfl_xor_sync(0xffffffffu, best[m], off);
            int oi = __shfl_xor_sync(0xffffffffu, bidx[m], off);
            if (ob > best[m] || (ob == best[m] && oi < bidx[m])) { best[m] = ob; bidx[m] = oi; }
        }
    }
    __syncthreads();
    if (tx == 0) {
#pragma unroll
        for (int m = 0; m < 8; m++) shIdx[ty * 8 + m] = bidx[m];
    }
    __syncthreads();

    if (tid < BM) {
        int id = shIdx[tid];
        outIdx[base + tid] = (float)id;
        atomicAdd(&g_counts[id], 1u);
    }
    float lsum = 0.0f;
#pragma unroll 8
    for (int it = 0; it < 32; it++) {
        int i = tid + it * 256;
        int row = i >> 6;
        int c = i & 63;
        int id = shIdx[row];
        float l = As[row * CD + c];
        float q = __ldg(&emb[(size_t)c * NCODES + id]);
        outQ[(size_t)(base + row) * CD + c] = l + (q - l);
        float d = q - l;
        lsum += d * d;
        atomicAdd(&g_dw[(size_t)c * NCODES + id], l);
    }
    shRed[tid] = lsum;
    __syncthreads();
    for (int s = 128; s > 0; s >>= 1) {
        if (tid < s) shRed[tid] += shRed[tid + s];
        __syncthreads();
    }
    if (tid == 0) atomicAdd(&g_loss[0], shRed[0]);
}

// ---------------- finalize ----------------
__global__ void __launch_bounds__(1024)
finalize_kernel(const float* __restrict__ ema_cluster,
                const float* __restrict__ ema_dw,
                float* __restrict__ out) {
    constexpr size_t LOSS_OFF = (size_t)NTOK * DIM_C;
    constexpr size_t PERP_OFF = LOSS_OFF + 1;
    constexpr size_t IDX_OFF = PERP_OFF + 1;
    constexpr size_t EMB_OFF = IDX_OFF + (size_t)NTOK;

    __shared__ float red[1024];
    int k = threadIdx.x;
    float debias = (float)(1.0 - pow(0.99, 1001.0));

    float cnt = (float)g_counts[k];
    float clh = ema_cluster[k] * DECAY_F + cnt * (1.0f - DECAY_F);
    float cs = clh / debias;

    red[k] = cs;
    __syncthreads();
    for (int s = 512; s > 0; s >>= 1) {
        if (k < s) red[k] += red[k + s];
        __syncthreads();
    }
    float n = red[0];
    __syncthreads();

    float p = cnt / (float)NTOK;
    red[k] = p * logf(p + 1e-10f);
    __syncthreads();
    for (int s = 512; s > 0; s >>= 1) {
        if (k < s) red[k] += red[k + s];
        __syncthreads();
    }
    float pl = red[0];

    float stable = (cs + 1e-5f) / (n + (float)NCODES * 1e-5f) * n;
#pragma unroll 4
    for (int c = 0; c < DIM_C; c++) {
        size_t i = (size_t)c * NCODES + k;
        float upd = (ema_dw[i] * DECAY_F + g_dw[i] * (1.0f - DECAY_F)) / debias;
        out[EMB_OFF + i] = upd / stable;
    }
    if (k == 0) {
        out[LOSS_OFF] = 0.25f * (g_loss[0] / ((float)NTOK * (float)DIM_C));
        out[PERP_OFF] = expf(-pl);
    }
}

// ---------------- launch ----------------
extern "C" void kernel_launch(void* const* d_in, const int* in_sizes, int n_in,
                              void* d_out, int out_size) {
    const float* states = (const float*)d_in[0];
    const float* w_se = (const float*)d_in[1];
    const float* b_se = (const float*)d_in[2];
    const float* w0 = (const float*)d_in[3];
    const float* b0 = (const float*)d_in[4];
    const float* w1 = (const float*)d_in[5];
    const float* b1 = (const float*)d_in[6];
    const float* w2 = (const float*)d_in[7];
    const float* b2 = (const float*)d_in[8];
    const float* emb = (const float*)d_in[9];
    const float* ema_cluster = (const float*)d_in[10];
    const float* ema_dw = (const float*)d_in[11];
    float* out = (float*)d_out;

    float *bufA, *bufB;
    __nv_bfloat16 *wb1, *wb2, *wb3;
    cudaGetSymbolAddress((void**)&bufA, g_bufA);
    cudaGetSymbolAddress((void**)&bufB, g_bufB);
    cudaGetSymbolAddress((void**)&wb1, g_wb1);
    cudaGetSymbolAddress((void**)&wb2, g_wb2);
    cudaGetSymbolAddress((void**)&wb3, g_wb3);

    const size_t IDX_OFF = (size_t)NTOK * DIM_C + 2;

    const int MMA_SMEM = 2 * (3 * 128 * 48 + 3 * 128 * 48);  // 73728
    cudaFuncSetAttribute(mma_gemm_gelu,
                         cudaFuncAttributeMaxDynamicSharedMemorySize, MMA_SMEM);
    cudaFuncSetAttribute(vq_fused_kernel,
                         cudaFuncAttributeMaxDynamicSharedMemorySize, VQ_SMEM_B);

    split_w_all<<<(WSPLIT_TOTAL + 255) / 256, 256>>>(w_se, w0, w1, w2, wb1, wb2, wb3);
    prep_kernel<<<64, 1024>>>(emb);

    dim3 blk(256);
    mma_gemm_gelu<<<dim3(DIM_E / 128, NTOK / 128), blk, MMA_SMEM>>>(
        states, wb1, wb2, wb3, b_se, bufA, DIM_D, DIM_E);
    mma_gemm_gelu<<<dim3(DIM_H / 128, NTOK / 128), blk, MMA_SMEM>>>(
        bufA, wb1 + 131072, wb2 + 131072, wb3 + 131072, b0, bufB, DIM_E, DIM_H);
    mma_gemm_gelu<<<dim3(DIM_H / 128, NTOK / 128), blk, MMA_SMEM>>>(
        bufB, wb1 + 393216, wb2 + 393216, wb3 + 393216, b1, bufA, DIM_H, DIM_H);

    vq_fused_kernel<<<NTOK / 128, blk, VQ_SMEM_B>>>(
        bufA, wb1 + 655360, wb2 + 655360, wb3 + 655360, b2, emb,
        out /*quantized*/, out + IDX_OFF);
    finalize_kernel<<<1, 1024>>>(ema_cluster, ema_dw, out);
}